// round 13
// baseline (speedup 1.0000x reference)
#include <cuda_runtime.h>
#include <cuda_fp16.h>
#include <cstdint>

// Problem shapes (fixed by the dataset)
#define T_DIM 2048
#define H_DIM 1024
#define E_DIM 8
#define FFN_DIM 1408
#define FFN2_DIM 2816
#define NPAIR 4096
#define NPAD (NPAIR + 128)

// ---------------- scratch (device globals) ----------------------------------
__device__ int   g_topk_idx[T_DIM * 2];
__device__ float g_topk_w[T_DIM * 2];
__device__ int   g_tok[NPAIR];
__device__ int   g_slot[T_DIM * 2];
__device__ int   g_base[E_DIM];
__device__ int   g_cnt[E_DIM];
__device__ __align__(16) __half g_xh[(size_t)T_DIM * H_DIM];               // token rows (half)
__device__ __align__(16) __half g_acth[(size_t)NPAD * FFN_DIM];
__device__ __align__(16) float  g_y[(size_t)NPAIR * H_DIM];
__device__ __align__(16) __half g_w1h[(size_t)E_DIM * H_DIM * FFN2_DIM];   // native [k][n]
__device__ __align__(16) __half g_w2h[(size_t)E_DIM * FFN_DIM * H_DIM];    // native [k][n]

// ---------------- helpers ----------------------------------------------------
__device__ __forceinline__ uint32_t smem_u32(const void* p) {
    uint32_t a;
    asm("{ .reg .u64 t; cvta.to.shared.u64 t, %1; cvt.u32.u64 %0, t; }"
        : "=r"(a) : "l"(p));
    return a;
}
__device__ __forceinline__ void cpa16(uint32_t dst, const void* src) {
    asm volatile("cp.async.cg.shared.global [%0], [%1], 16;" :: "r"(dst), "l"(src));
}
#define CPCOMMIT() asm volatile("cp.async.commit_group;" ::: "memory")
#define CPWAIT2()  asm volatile("cp.async.wait_group 2;" ::: "memory")

__device__ __forceinline__ void ldm4(uint32_t* f, uint32_t a) {
    asm volatile("ldmatrix.sync.aligned.m8n8.x4.shared.b16 {%0,%1,%2,%3}, [%4];"
                 : "=r"(f[0]), "=r"(f[1]), "=r"(f[2]), "=r"(f[3]) : "r"(a));
}
__device__ __forceinline__ void ldm4t(uint32_t* f, uint32_t a) {
    asm volatile("ldmatrix.sync.aligned.m8n8.x4.trans.shared.b16 {%0,%1,%2,%3}, [%4];"
                 : "=r"(f[0]), "=r"(f[1]), "=r"(f[2]), "=r"(f[3]) : "r"(a));
}
__device__ __forceinline__ void mma16(float* c, const uint32_t* a,
                                      uint32_t b0, uint32_t b1) {
    asm volatile(
        "mma.sync.aligned.m16n8k16.row.col.f32.f16.f16.f32 "
        "{%0,%1,%2,%3}, {%4,%5,%6,%7}, {%8,%9}, {%0,%1,%2,%3};"
        : "+f"(c[0]), "+f"(c[1]), "+f"(c[2]), "+f"(c[3])
        : "r"(a[0]), "r"(a[1]), "r"(a[2]), "r"(a[3]), "r"(b0), "r"(b1));
}

// stage: A [128 m][64 k] half = 16KB at +0 ; B [64 k][256 n] half = 32KB at +16384
#define STAGE_BYTES 49152u
#define NSTAGE 4
#define SMEM_BYTES (NSTAGE * STAGE_BYTES)   // 196608
#define GTHREADS 512

// ---------------- gate: softmax top-2 + half conversion of the token row ----
__global__ void __launch_bounds__(256) gate_kernel(
    const float* __restrict__ x, const float* __restrict__ gw)
{
    int t = blockIdx.x;
    const float* xr = x + (size_t)t * H_DIM;
    int wid = threadIdx.x >> 5, lane = threadIdx.x & 31;
    __shared__ float sc[E_DIM];

    {
        float4 v = ((const float4*)xr)[threadIdx.x];
        __half2* d = (__half2*)(g_xh + (size_t)t * H_DIM);
        d[threadIdx.x * 2]     = __floats2half2_rn(v.x, v.y);
        d[threadIdx.x * 2 + 1] = __floats2half2_rn(v.z, v.w);
    }

    const float* g = gw + (size_t)wid * H_DIM;
    float s = 0.f;
    for (int i = lane; i < H_DIM; i += 32) s += xr[i] * g[i];
#pragma unroll
    for (int o = 16; o; o >>= 1) s += __shfl_xor_sync(0xffffffffu, s, o);
    if (lane == 0) sc[wid] = s;
    __syncthreads();

    if (threadIdx.x == 0) {
        float m = -1e30f;
#pragma unroll
        for (int e = 0; e < E_DIM; e++) m = fmaxf(m, sc[e]);
        float p[E_DIM], den = 0.f;
#pragma unroll
        for (int e = 0; e < E_DIM; e++) { p[e] = __expf(sc[e] - m); den += p[e]; }
        int i0 = 0;
#pragma unroll
        for (int e = 1; e < E_DIM; e++) if (p[e] > p[i0]) i0 = e;
        int i1 = -1;
#pragma unroll
        for (int e = 0; e < E_DIM; e++)
            if (e != i0 && (i1 < 0 || p[e] > p[i1])) i1 = e;
        float q0 = p[i0] / den, q1 = p[i1] / den;
        float wsum = q0 + q1 + 1e-20f;
        g_topk_idx[2 * t]     = i0;
        g_topk_idx[2 * t + 1] = i1;
        g_topk_w[2 * t]       = q0 / wsum;
        g_topk_w[2 * t + 1]   = q1 / wsum;
    }
}

// ---------------- scatter: deterministic compaction by expert --------------
__global__ void __launch_bounds__(256) scatter_kernel()
{
    int wid = threadIdx.x >> 5, lane = threadIdx.x & 31;
    __shared__ int scnt[E_DIM];

    int c = 0;
    for (int baset = 0; baset < T_DIM; baset += 32) {
        int t = baset + lane;
        bool m = (g_topk_idx[2 * t] == wid) || (g_topk_idx[2 * t + 1] == wid);
        unsigned b = __ballot_sync(0xffffffffu, m);
        c += __popc(b);
    }
    if (lane == 0) scnt[wid] = c;
    __syncthreads();
    if (threadIdx.x == 0) {
        int acc = 0;
        for (int e = 0; e < E_DIM; e++) { g_base[e] = acc; g_cnt[e] = scnt[e]; acc += scnt[e]; }
    }
    __syncthreads();

    int pos = g_base[wid];
    for (int baset = 0; baset < T_DIM; baset += 32) {
        int t = baset + lane;
        int k = -1;
        if (g_topk_idx[2 * t] == wid) k = 0;
        else if (g_topk_idx[2 * t + 1] == wid) k = 1;
        unsigned b = __ballot_sync(0xffffffffu, k >= 0);
        int off = __popc(b & ((1u << lane) - 1u));
        if (k >= 0) {
            g_tok[pos + off] = t;
            g_slot[2 * t + k] = pos + off;
        }
        pos += __popc(b);
    }
}

// ---------------- streaming f32 -> f16 cast ---------------------------------
__global__ void __launch_bounds__(256) convW_kernel(
    const float* __restrict__ src, __half* __restrict__ dst, size_t n4)
{
    size_t i = (size_t)blockIdx.x * blockDim.x + threadIdx.x;
    size_t stride = (size_t)gridDim.x * blockDim.x;
    for (; i < n4; i += stride) {
        float4 v = ((const float4*)src)[i];
        __half2 h0 = __floats2half2_rn(v.x, v.y);
        __half2 h1 = __floats2half2_rn(v.z, v.w);
        ((uint2*)dst)[i] = make_uint2(*(uint32_t*)&h0, *(uint32_t*)&h1);
    }
}

// ---------------- GEMM1: x_tok rows @ w1h([k][n]) -> swiglu -> g_acth -------
// CTA: 128 M x 128 FFN cols; 512 threads, 16 warps (4m x 4n), warp 32 x 64.
// Handles experts [e0, e0 + gridDim.z).
__global__ void __launch_bounds__(GTHREADS) gemm1_kernel(int e0)
{
    int e = e0 + blockIdx.z;
    int cnt = g_cnt[e];
    int m0 = blockIdx.y * 128;
    if (m0 >= cnt) return;
    int base = g_base[e];
    int n0 = blockIdx.x * 128;

    extern __shared__ char smem[];
    uint32_t sb = smem_u32(smem);
    int tid = threadIdx.x, lane = tid & 31, wid = tid >> 5;
    int wm = wid >> 2, wn = wid & 3;     // 4 x 4 warps

    uint32_t adst[2]; const __half* asrc[2];
#pragma unroll
    for (int i = 0; i < 2; i++) {
        int idx = tid + (i << 9);
        int r = idx >> 3, c = idx & 7;
        adst[i] = (uint32_t)(r * 128 + ((c ^ (r & 7)) << 4));
        int pr = base + m0 + r;
        if (pr > NPAIR - 1) pr = NPAIR - 1;
        int tok = g_tok[pr];
        asrc[i] = g_xh + (size_t)tok * H_DIM + c * 8;
    }
    uint32_t bdst[4]; const __half* bsrc[4];
    const __half* w1e = g_w1h + (size_t)e * ((size_t)H_DIM * FFN2_DIM);
#pragma unroll
    for (int i = 0; i < 4; i++) {
        int idx = tid + (i << 9);
        int r = idx >> 5, c = idx & 31;
        bdst[i] = (uint32_t)(r * 512 + ((((c & 24) | ((c ^ r) & 7))) << 4));
        int col = (c < 16) ? (n0 + c * 8) : (FFN_DIM + n0 + (c - 16) * 8);
        bsrc[i] = w1e + (size_t)r * FFN2_DIM + col;
    }

    auto load_stage = [&](int t) {
        uint32_t ab = sb + (uint32_t)(t & 3) * STAGE_BYTES;
        uint32_t bb = ab + 16384u;
        int k0 = t * 64;
#pragma unroll
        for (int i = 0; i < 2; i++) cpa16(ab + adst[i], asrc[i] + k0);
#pragma unroll
        for (int i = 0; i < 4; i++) cpa16(bb + bdst[i], bsrc[i] + (size_t)k0 * FFN2_DIM);
    };

    uint32_t aoffr = (uint32_t)((wm * 32 + (lane & 15)) * 128);
    uint32_t cxb = (uint32_t)(lane >> 4), rx = (uint32_t)(lane & 7);
    uint32_t klocal = ((lane >> 3) & 1) * 8 + (lane & 7);
    uint32_t bbase[4];
#pragma unroll
    for (int p = 0; p < 4; p++) {
        uint32_t u = (p < 2) ? (uint32_t)(wn * 4 + p * 2)
                             : (uint32_t)(16 + wn * 4 + (p - 2) * 2);
        uint32_t unit = u + (uint32_t)(lane >> 4);
        uint32_t usw = (unit & 24) | ((unit ^ (lane & 7)) & 7);
        bbase[p] = klocal * 512 + (usw << 4);
    }

    float acc[2][8][4] = {};

    load_stage(0); CPCOMMIT();
    load_stage(1); CPCOMMIT();
    load_stage(2); CPCOMMIT();

    const int NS = H_DIM / 64;  // 16
    for (int s = 0; s < NS; s++) {
        CPWAIT2();
        __syncthreads();
        if (s + 3 < NS) load_stage(s + 3);
        CPCOMMIT();
        uint32_t ab = sb + (uint32_t)(s & 3) * STAGE_BYTES;
        uint32_t bb = ab + 16384u;
#pragma unroll
        for (int kk = 0; kk < 4; kk++) {
            uint32_t cx = ((((uint32_t)kk << 1) + cxb) ^ rx) << 4;
            uint32_t af[2][4], bf[4][4];
#pragma unroll
            for (int mt = 0; mt < 2; mt++) ldm4(af[mt], ab + aoffr + mt * 2048 + cx);
#pragma unroll
            for (int p = 0; p < 4; p++) ldm4t(bf[p], bb + bbase[p] + (uint32_t)kk * 8192);
#pragma unroll
            for (int mt = 0; mt < 2; mt++)
#pragma unroll
                for (int p = 0; p < 4; p++) {
                    mma16(acc[mt][2 * p],     af[mt], bf[p][0], bf[p][1]);
                    mma16(acc[mt][2 * p + 1], af[mt], bf[p][2], bf[p][3]);
                }
        }
    }

    // epilogue: swiglu, store half
    int gid = lane >> 2, tig = lane & 3;
#pragma unroll
    for (int mt = 0; mt < 2; mt++) {
        int r1 = m0 + wm * 32 + mt * 16 + gid;
#pragma unroll
        for (int j = 0; j < 4; j++) {
            int col = n0 + wn * 32 + j * 8 + tig * 2;
            float g0 = acc[mt][j][0], g1 = acc[mt][j][1];
            float u0 = acc[mt][j + 4][0], u1 = acc[mt][j + 4][1];
            if (r1 < cnt) {
                __half2 h = __floats2half2_rn(g0 * u0 / (1.f + __expf(-g0)),
                                              g1 * u1 / (1.f + __expf(-g1)));
                *(__half2*)&g_acth[(size_t)(base + r1) * FFN_DIM + col] = h;
            }
            float g2 = acc[mt][j][2], g3 = acc[mt][j][3];
            float u2 = acc[mt][j + 4][2], u3 = acc[mt][j + 4][3];
            if (r1 + 8 < cnt) {
                __half2 h = __floats2half2_rn(g2 * u2 / (1.f + __expf(-g2)),
                                              g3 * u3 / (1.f + __expf(-g3)));
                *(__half2*)&g_acth[(size_t)(base + r1 + 8) * FFN_DIM + col] = h;
            }
        }
    }
}

// ---------------- GEMM2: g_acth[128,1408] @ w2h([k][n]) -> g_y --------------
// CTA: 128 M x 256 N; 512 threads, 16 warps (4m x 4n), warp 32 x 64.
__global__ void __launch_bounds__(GTHREADS) gemm2_kernel(int e0)
{
    int e = e0 + blockIdx.z;
    int cnt = g_cnt[e];
    int m0 = blockIdx.y * 128;
    if (m0 >= cnt) return;
    int base = g_base[e];
    int n0 = blockIdx.x * 256;

    extern __shared__ char smem[];
    uint32_t sb = smem_u32(smem);
    int tid = threadIdx.x, lane = tid & 31, wid = tid >> 5;
    int wm = wid >> 2, wn = wid & 3;

    uint32_t adst[2]; const __half* asrc[2];
#pragma unroll
    for (int i = 0; i < 2; i++) {
        int idx = tid + (i << 9);
        int r = idx >> 3, c = idx & 7;
        adst[i] = (uint32_t)(r * 128 + ((c ^ (r & 7)) << 4));
        asrc[i] = g_acth + (size_t)(base + m0 + r) * FFN_DIM + c * 8;
    }
    uint32_t bdst[4]; const __half* bsrc[4];
    const __half* w2e = g_w2h + (size_t)e * ((size_t)FFN_DIM * H_DIM);
#pragma unroll
    for (int i = 0; i < 4; i++) {
        int idx = tid + (i << 9);
        int r = idx >> 5, c = idx & 31;
        bdst[i] = (uint32_t)(r * 512 + ((((c & 24) | ((c ^ r) & 7))) << 4));
        bsrc[i] = w2e + (size_t)r * H_DIM + n0 + c * 8;
    }

    auto load_stage = [&](int t) {
        uint32_t ab = sb + (uint32_t)(t & 3) * STAGE_BYTES;
        uint32_t bb = ab + 16384u;
        int k0 = t * 64;
#pragma unroll
        for (int i = 0; i < 2; i++) cpa16(ab + adst[i], asrc[i] + k0);
#pragma unroll
        for (int i = 0; i < 4; i++) cpa16(bb + bdst[i], bsrc[i] + (size_t)k0 * H_DIM);
    };

    uint32_t aoffr = (uint32_t)((wm * 32 + (lane & 15)) * 128);
    uint32_t cxb = (uint32_t)(lane >> 4), rx = (uint32_t)(lane & 7);
    uint32_t klocal = ((lane >> 3) & 1) * 8 + (lane & 7);
    uint32_t bbase[4];
#pragma unroll
    for (int p = 0; p < 4; p++) {
        uint32_t unit = (uint32_t)(wn * 8 + p * 2) + (uint32_t)(lane >> 4);
        uint32_t usw = (unit & 24) | ((unit ^ (lane & 7)) & 7);
        bbase[p] = klocal * 512 + (usw << 4);
    }

    float acc[2][8][4] = {};

    load_stage(0); CPCOMMIT();
    load_stage(1); CPCOMMIT();
    load_stage(2); CPCOMMIT();

    const int NS = FFN_DIM / 64;  // 22
    for (int s = 0; s < NS; s++) {
        CPWAIT2();
        __syncthreads();
        if (s + 3 < NS) load_stage(s + 3);
        CPCOMMIT();
        uint32_t ab = sb + (uint32_t)(s & 3) * STAGE_BYTES;
        uint32_t bb = ab + 16384u;
#pragma unroll
        for (int kk = 0; kk < 4; kk++) {
            uint32_t cx = ((((uint32_t)kk << 1) + cxb) ^ rx) << 4;
            uint32_t af[2][4], bf[4][4];
#pragma unroll
            for (int mt = 0; mt < 2; mt++) ldm4(af[mt], ab + aoffr + mt * 2048 + cx);
#pragma unroll
            for (int p = 0; p < 4; p++) ldm4t(bf[p], bb + bbase[p] + (uint32_t)kk * 8192);
#pragma unroll
            for (int mt = 0; mt < 2; mt++)
#pragma unroll
                for (int p = 0; p < 4; p++) {
                    mma16(acc[mt][2 * p],     af[mt], bf[p][0], bf[p][1]);
                    mma16(acc[mt][2 * p + 1], af[mt], bf[p][2], bf[p][3]);
                }
        }
    }

    int gid = lane >> 2, tig = lane & 3;
#pragma unroll
    for (int mt = 0; mt < 2; mt++) {
        int r1 = m0 + wm * 32 + mt * 16 + gid;
#pragma unroll
        for (int j = 0; j < 8; j++) {
            int col = n0 + wn * 64 + j * 8 + tig * 2;
            if (r1 < cnt) {
                float2 o = make_float2(acc[mt][j][0], acc[mt][j][1]);
                *(float2*)&g_y[(size_t)(base + r1) * H_DIM + col] = o;
            }
            if (r1 + 8 < cnt) {
                float2 o = make_float2(acc[mt][j][2], acc[mt][j][3]);
                *(float2*)&g_y[(size_t)(base + r1 + 8) * H_DIM + col] = o;
            }
        }
    }
}

// ---------------- combine: out[t] = w0*Y[slot0] + w1*Y[slot1] --------------
__global__ void __launch_bounds__(256) combine_kernel(float* __restrict__ out)
{
    int t = blockIdx.x;
    int s0 = g_slot[2 * t], s1 = g_slot[2 * t + 1];
    float w0 = g_topk_w[2 * t], w1 = g_topk_w[2 * t + 1];
    const float* y0 = g_y + (size_t)s0 * H_DIM;
    const float* y1 = g_y + (size_t)s1 * H_DIM;
    float* orow = out + (size_t)t * H_DIM;

    int h = threadIdx.x * 4;
    float4 a = *(const float4*)(y0 + h);
    float4 b = *(const float4*)(y1 + h);
    float4 o;
    o.x = w0 * a.x + w1 * b.x;
    o.y = w0 * a.y + w1 * b.y;
    o.z = w0 * a.z + w1 * b.z;
    o.w = w0 * a.w + w1 * b.w;
    *(float4*)(orow + h) = o;
}

// ---------------- launch ----------------------------------------------------
extern "C" void kernel_launch(void* const* d_in, const int* in_sizes, int n_in,
                              void* d_out, int out_size)
{
    const float* hidden = (const float*)d_in[0];   // [S, B, H] == [T, H]
    const float* gate_w = (const float*)d_in[1];   // [E, H]
    const float* w1     = (const float*)d_in[2];   // [E, H, 2*FFN]
    const float* w2     = (const float*)d_in[3];   // [E, FFN, H]
    float* out          = (float*)d_out;

    static cudaStream_t sW = nullptr, sB = nullptr;
    static cudaEvent_t ev_fork = nullptr, ev_w1 = nullptr, ev_w2 = nullptr,
                       ev_g1a = nullptr, ev_g1b = nullptr, ev_g2 = nullptr;
    static bool attr_done = false;
    if (!sW) {
        cudaStreamCreateWithFlags(&sW, cudaStreamNonBlocking);
        cudaStreamCreateWithFlags(&sB, cudaStreamNonBlocking);
        cudaEventCreateWithFlags(&ev_fork, cudaEventDisableTiming);
        cudaEventCreateWithFlags(&ev_w1, cudaEventDisableTiming);
        cudaEventCreateWithFlags(&ev_w2, cudaEventDisableTiming);
        cudaEventCreateWithFlags(&ev_g1a, cudaEventDisableTiming);
        cudaEventCreateWithFlags(&ev_g1b, cudaEventDisableTiming);
        cudaEventCreateWithFlags(&ev_g2, cudaEventDisableTiming);
    }
    if (!attr_done) {
        cudaFuncSetAttribute(gemm1_kernel, cudaFuncAttributeMaxDynamicSharedMemorySize, SMEM_BYTES);
        cudaFuncSetAttribute(gemm2_kernel, cudaFuncAttributeMaxDynamicSharedMemorySize, SMEM_BYTES);
        attr_done = true;
    }

    __half* w1h; cudaGetSymbolAddress((void**)&w1h, g_w1h);
    __half* w2h; cudaGetSymbolAddress((void**)&w2h, g_w2h);

    // Fork: weight casts on sW (w1 first — gemm1 only needs w1h).
    cudaEventRecord(ev_fork, 0);
    cudaStreamWaitEvent(sW, ev_fork, 0);
    convW_kernel<<<2048, 256, 0, sW>>>(w1, w1h, (size_t)E_DIM * H_DIM * FFN2_DIM / 4);
    cudaEventRecord(ev_w1, sW);
    convW_kernel<<<2048, 256, 0, sW>>>(w2, w2h, (size_t)E_DIM * FFN_DIM * H_DIM / 4);
    cudaEventRecord(ev_w2, sW);

    gate_kernel<<<T_DIM, 256>>>(hidden, gate_w);   // also writes g_xh (half)
    scatter_kernel<<<1, 256>>>();

    // GEMM1 in two expert halves on stream 0 (needs w1h only).
    cudaStreamWaitEvent(0, ev_w1, 0);
    gemm1_kernel<<<dim3(FFN_DIM / 128, NPAIR / 128, 4), GTHREADS, SMEM_BYTES>>>(0);
    cudaEventRecord(ev_g1a, 0);
    gemm1_kernel<<<dim3(FFN_DIM / 128, NPAIR / 128, 4), GTHREADS, SMEM_BYTES>>>(4);
    cudaEventRecord(ev_g1b, 0);

    // GEMM2 halves on sB: first half overlaps gemm1's second half.
    cudaStreamWaitEvent(sB, ev_w2, 0);
    cudaStreamWaitEvent(sB, ev_g1a, 0);
    gemm2_kernel<<<dim3(H_DIM / 256, NPAIR / 128, 4), GTHREADS, SMEM_BYTES, sB>>>(0);
    cudaStreamWaitEvent(sB, ev_g1b, 0);
    gemm2_kernel<<<dim3(H_DIM / 256, NPAIR / 128, 4), GTHREADS, SMEM_BYTES, sB>>>(4);
    cudaEventRecord(ev_g2, sB);

    cudaStreamWaitEvent(0, ev_g2, 0);
    combine_kernel<<<T_DIM, 256>>>(out);
}

// round 14
// speedup vs baseline: 1.2442x; 1.2442x over previous
#include <cuda_runtime.h>
#include <cuda_fp16.h>
#include <cstdint>

// Problem shapes (fixed by the dataset)
#define T_DIM 2048
#define H_DIM 1024
#define E_DIM 8
#define FFN_DIM 1408
#define FFN2_DIM 2816
#define NPAIR 4096
#define NPAD (NPAIR + 128)

// ---------------- scratch (device globals) ----------------------------------
__device__ int   g_topk_idx[T_DIM * 2];
__device__ float g_topk_w[T_DIM * 2];
__device__ int   g_tok[NPAIR];
__device__ int   g_slot[T_DIM * 2];
__device__ int   g_base[E_DIM];
__device__ int   g_cnt[E_DIM];
__device__ __align__(16) __half g_xh[(size_t)T_DIM * H_DIM];               // token rows (half)
__device__ __align__(16) __half g_acth[(size_t)NPAD * FFN_DIM];
__device__ __align__(16) float  g_y[(size_t)NPAIR * H_DIM];
__device__ __align__(16) __half g_w1h[(size_t)E_DIM * H_DIM * FFN2_DIM];   // native [k][n]
__device__ __align__(16) __half g_w2h[(size_t)E_DIM * FFN_DIM * H_DIM];    // native [k][n]

// ---------------- helpers ----------------------------------------------------
__device__ __forceinline__ uint32_t smem_u32(const void* p) {
    uint32_t a;
    asm("{ .reg .u64 t; cvta.to.shared.u64 t, %1; cvt.u32.u64 %0, t; }"
        : "=r"(a) : "l"(p));
    return a;
}
__device__ __forceinline__ void cpa16(uint32_t dst, const void* src) {
    asm volatile("cp.async.cg.shared.global [%0], [%1], 16;" :: "r"(dst), "l"(src));
}
#define CPCOMMIT() asm volatile("cp.async.commit_group;" ::: "memory")
#define CPWAIT2()  asm volatile("cp.async.wait_group 2;" ::: "memory")

__device__ __forceinline__ void ldm4(uint32_t* f, uint32_t a) {
    asm volatile("ldmatrix.sync.aligned.m8n8.x4.shared.b16 {%0,%1,%2,%3}, [%4];"
                 : "=r"(f[0]), "=r"(f[1]), "=r"(f[2]), "=r"(f[3]) : "r"(a));
}
__device__ __forceinline__ void ldm4t(uint32_t* f, uint32_t a) {
    asm volatile("ldmatrix.sync.aligned.m8n8.x4.trans.shared.b16 {%0,%1,%2,%3}, [%4];"
                 : "=r"(f[0]), "=r"(f[1]), "=r"(f[2]), "=r"(f[3]) : "r"(a));
}
__device__ __forceinline__ void mma16(float* c, const uint32_t* a,
                                      uint32_t b0, uint32_t b1) {
    asm volatile(
        "mma.sync.aligned.m16n8k16.row.col.f32.f16.f16.f32 "
        "{%0,%1,%2,%3}, {%4,%5,%6,%7}, {%8,%9}, {%0,%1,%2,%3};"
        : "+f"(c[0]), "+f"(c[1]), "+f"(c[2]), "+f"(c[3])
        : "r"(a[0]), "r"(a[1]), "r"(a[2]), "r"(a[3]), "r"(b0), "r"(b1));
}

// stage: A [128 m][64 k] half = 16KB at +0 ; B [64 k][256 n] half = 32KB at +16384
#define STAGE_BYTES 49152u
#define NSTAGE 4
#define SMEM_BYTES (NSTAGE * STAGE_BYTES)   // 196608
#define GTHREADS 512

// ---------------- init: zero per-expert counters -----------------------------
__global__ void init_kernel()
{
    if (threadIdx.x < E_DIM) g_cnt[threadIdx.x] = 0;
}

// ---------------- gate: softmax top-2 + half conversion + expert counts ------
__global__ void __launch_bounds__(256) gate_kernel(
    const float* __restrict__ x, const float* __restrict__ gw)
{
    int t = blockIdx.x;
    const float* xr = x + (size_t)t * H_DIM;
    int wid = threadIdx.x >> 5, lane = threadIdx.x & 31;
    __shared__ float sc[E_DIM];

    {
        float4 v = ((const float4*)xr)[threadIdx.x];
        __half2* d = (__half2*)(g_xh + (size_t)t * H_DIM);
        d[threadIdx.x * 2]     = __floats2half2_rn(v.x, v.y);
        d[threadIdx.x * 2 + 1] = __floats2half2_rn(v.z, v.w);
    }

    const float* g = gw + (size_t)wid * H_DIM;
    float s = 0.f;
    for (int i = lane; i < H_DIM; i += 32) s += xr[i] * g[i];
#pragma unroll
    for (int o = 16; o; o >>= 1) s += __shfl_xor_sync(0xffffffffu, s, o);
    if (lane == 0) sc[wid] = s;
    __syncthreads();

    if (threadIdx.x == 0) {
        float m = -1e30f;
#pragma unroll
        for (int e = 0; e < E_DIM; e++) m = fmaxf(m, sc[e]);
        float p[E_DIM], den = 0.f;
#pragma unroll
        for (int e = 0; e < E_DIM; e++) { p[e] = __expf(sc[e] - m); den += p[e]; }
        int i0 = 0;
#pragma unroll
        for (int e = 1; e < E_DIM; e++) if (p[e] > p[i0]) i0 = e;
        int i1 = -1;
#pragma unroll
        for (int e = 0; e < E_DIM; e++)
            if (e != i0 && (i1 < 0 || p[e] > p[i1])) i1 = e;
        float q0 = p[i0] / den, q1 = p[i1] / den;
        float wsum = q0 + q1 + 1e-20f;
        g_topk_idx[2 * t]     = i0;
        g_topk_idx[2 * t + 1] = i1;
        g_topk_w[2 * t]       = q0 / wsum;
        g_topk_w[2 * t + 1]   = q1 / wsum;
        atomicAdd(&g_cnt[i0], 1);           // order-independent -> deterministic
        atomicAdd(&g_cnt[i1], 1);
    }
}

// ---------------- scatter: 8 blocks (one expert each), stable compaction ----
__global__ void __launch_bounds__(256) scatter_kernel()
{
    int e = blockIdx.x;
    int wid = threadIdx.x >> 5, lane = threadIdx.x & 31;
    __shared__ int swcnt[8];
    __shared__ int sbase;

    // pass 1: per-warp slice counts (warp w covers tokens [w*256, w*256+256))
    int c = 0;
#pragma unroll
    for (int i = 0; i < 8; i++) {
        int t = wid * 256 + i * 32 + lane;
        bool m = (g_topk_idx[2 * t] == e) || (g_topk_idx[2 * t + 1] == e);
        unsigned b = __ballot_sync(0xffffffffu, m);
        c += __popc(b);
    }
    if (lane == 0) swcnt[wid] = c;
    __syncthreads();
    if (threadIdx.x == 0) {
        int b = 0;
        for (int i = 0; i < e; i++) b += g_cnt[i];
        g_base[e] = b;
        sbase = b;
        int acc = 0;
        for (int w = 0; w < 8; w++) { int cc = swcnt[w]; swcnt[w] = acc; acc += cc; }
    }
    __syncthreads();

    // pass 2: stable append within slice
    int pos = sbase + swcnt[wid];
#pragma unroll
    for (int i = 0; i < 8; i++) {
        int t = wid * 256 + i * 32 + lane;
        int k = -1;
        if (g_topk_idx[2 * t] == e) k = 0;
        else if (g_topk_idx[2 * t + 1] == e) k = 1;
        unsigned b = __ballot_sync(0xffffffffu, k >= 0);
        int off = __popc(b & ((1u << lane) - 1u));
        if (k >= 0) {
            g_tok[pos + off] = t;
            g_slot[2 * t + k] = pos + off;
        }
        pos += __popc(b);
    }
}

// ---------------- streaming f32 -> f16 cast ---------------------------------
__global__ void __launch_bounds__(256) convW_kernel(
    const float* __restrict__ src, __half* __restrict__ dst, size_t n4)
{
    size_t i = (size_t)blockIdx.x * blockDim.x + threadIdx.x;
    size_t stride = (size_t)gridDim.x * blockDim.x;
    for (; i < n4; i += stride) {
        float4 v = ((const float4*)src)[i];
        __half2 h0 = __floats2half2_rn(v.x, v.y);
        __half2 h1 = __floats2half2_rn(v.z, v.w);
        ((uint2*)dst)[i] = make_uint2(*(uint32_t*)&h0, *(uint32_t*)&h1);
    }
}

// ---------------- GEMM1: x_tok rows @ w1h([k][n]) -> swiglu -> g_acth -------
// CTA: 128 M x 128 FFN cols; 512 threads, 16 warps (4m x 4n), warp 32 x 64.
__global__ void __launch_bounds__(GTHREADS) gemm1_kernel()
{
    int e = blockIdx.z;
    int cnt = g_cnt[e];
    int m0 = blockIdx.y * 128;
    if (m0 >= cnt) return;
    int base = g_base[e];
    int n0 = blockIdx.x * 128;

    extern __shared__ char smem[];
    uint32_t sb = smem_u32(smem);
    int tid = threadIdx.x, lane = tid & 31, wid = tid >> 5;
    int wm = wid >> 2, wn = wid & 3;     // 4 x 4 warps

    uint32_t adst[2]; const __half* asrc[2];
#pragma unroll
    for (int i = 0; i < 2; i++) {
        int idx = tid + (i << 9);
        int r = idx >> 3, c = idx & 7;
        adst[i] = (uint32_t)(r * 128 + ((c ^ (r & 7)) << 4));
        int pr = base + m0 + r;
        if (pr > NPAIR - 1) pr = NPAIR - 1;
        int tok = g_tok[pr];
        asrc[i] = g_xh + (size_t)tok * H_DIM + c * 8;
    }
    uint32_t bdst[4]; const __half* bsrc[4];
    const __half* w1e = g_w1h + (size_t)e * ((size_t)H_DIM * FFN2_DIM);
#pragma unroll
    for (int i = 0; i < 4; i++) {
        int idx = tid + (i << 9);
        int r = idx >> 5, c = idx & 31;
        bdst[i] = (uint32_t)(r * 512 + ((((c & 24) | ((c ^ r) & 7))) << 4));
        int col = (c < 16) ? (n0 + c * 8) : (FFN_DIM + n0 + (c - 16) * 8);
        bsrc[i] = w1e + (size_t)r * FFN2_DIM + col;
    }

    auto load_stage = [&](int t) {
        uint32_t ab = sb + (uint32_t)(t & 3) * STAGE_BYTES;
        uint32_t bb = ab + 16384u;
        int k0 = t * 64;
#pragma unroll
        for (int i = 0; i < 2; i++) cpa16(ab + adst[i], asrc[i] + k0);
#pragma unroll
        for (int i = 0; i < 4; i++) cpa16(bb + bdst[i], bsrc[i] + (size_t)k0 * FFN2_DIM);
    };

    uint32_t aoffr = (uint32_t)((wm * 32 + (lane & 15)) * 128);
    uint32_t cxb = (uint32_t)(lane >> 4), rx = (uint32_t)(lane & 7);
    uint32_t klocal = ((lane >> 3) & 1) * 8 + (lane & 7);
    uint32_t bbase[4];
#pragma unroll
    for (int p = 0; p < 4; p++) {
        uint32_t u = (p < 2) ? (uint32_t)(wn * 4 + p * 2)
                             : (uint32_t)(16 + wn * 4 + (p - 2) * 2);
        uint32_t unit = u + (uint32_t)(lane >> 4);
        uint32_t usw = (unit & 24) | ((unit ^ (lane & 7)) & 7);
        bbase[p] = klocal * 512 + (usw << 4);
    }

    float acc[2][8][4] = {};

    load_stage(0); CPCOMMIT();
    load_stage(1); CPCOMMIT();
    load_stage(2); CPCOMMIT();

    const int NS = H_DIM / 64;  // 16
    for (int s = 0; s < NS; s++) {
        CPWAIT2();
        __syncthreads();
        if (s + 3 < NS) load_stage(s + 3);
        CPCOMMIT();
        uint32_t ab = sb + (uint32_t)(s & 3) * STAGE_BYTES;
        uint32_t bb = ab + 16384u;
#pragma unroll
        for (int kk = 0; kk < 4; kk++) {
            uint32_t cx = ((((uint32_t)kk << 1) + cxb) ^ rx) << 4;
            uint32_t af[2][4], bf[4][4];
#pragma unroll
            for (int mt = 0; mt < 2; mt++) ldm4(af[mt], ab + aoffr + mt * 2048 + cx);
#pragma unroll
            for (int p = 0; p < 4; p++) ldm4t(bf[p], bb + bbase[p] + (uint32_t)kk * 8192);
#pragma unroll
            for (int mt = 0; mt < 2; mt++)
#pragma unroll
                for (int p = 0; p < 4; p++) {
                    mma16(acc[mt][2 * p],     af[mt], bf[p][0], bf[p][1]);
                    mma16(acc[mt][2 * p + 1], af[mt], bf[p][2], bf[p][3]);
                }
        }
    }

    // epilogue: swiglu, store half
    int gid = lane >> 2, tig = lane & 3;
#pragma unroll
    for (int mt = 0; mt < 2; mt++) {
        int r1 = m0 + wm * 32 + mt * 16 + gid;
#pragma unroll
        for (int j = 0; j < 4; j++) {
            int col = n0 + wn * 32 + j * 8 + tig * 2;
            float g0 = acc[mt][j][0], g1 = acc[mt][j][1];
            float u0 = acc[mt][j + 4][0], u1 = acc[mt][j + 4][1];
            if (r1 < cnt) {
                __half2 h = __floats2half2_rn(g0 * u0 / (1.f + __expf(-g0)),
                                              g1 * u1 / (1.f + __expf(-g1)));
                *(__half2*)&g_acth[(size_t)(base + r1) * FFN_DIM + col] = h;
            }
            float g2 = acc[mt][j][2], g3 = acc[mt][j][3];
            float u2 = acc[mt][j + 4][2], u3 = acc[mt][j + 4][3];
            if (r1 + 8 < cnt) {
                __half2 h = __floats2half2_rn(g2 * u2 / (1.f + __expf(-g2)),
                                              g3 * u3 / (1.f + __expf(-g3)));
                *(__half2*)&g_acth[(size_t)(base + r1 + 8) * FFN_DIM + col] = h;
            }
        }
    }
}

// ---------------- GEMM2: g_acth[128,1408] @ w2h([k][n]) -> g_y --------------
// CTA: 128 M x 256 N; 512 threads, 16 warps (4m x 4n), warp 32 x 64.
__global__ void __launch_bounds__(GTHREADS) gemm2_kernel()
{
    int e = blockIdx.z;
    int cnt = g_cnt[e];
    int m0 = blockIdx.y * 128;
    if (m0 >= cnt) return;
    int base = g_base[e];
    int n0 = blockIdx.x * 256;

    extern __shared__ char smem[];
    uint32_t sb = smem_u32(smem);
    int tid = threadIdx.x, lane = tid & 31, wid = tid >> 5;
    int wm = wid >> 2, wn = wid & 3;

    uint32_t adst[2]; const __half* asrc[2];
#pragma unroll
    for (int i = 0; i < 2; i++) {
        int idx = tid + (i << 9);
        int r = idx >> 3, c = idx & 7;
        adst[i] = (uint32_t)(r * 128 + ((c ^ (r & 7)) << 4));
        asrc[i] = g_acth + (size_t)(base + m0 + r) * FFN_DIM + c * 8;
    }
    uint32_t bdst[4]; const __half* bsrc[4];
    const __half* w2e = g_w2h + (size_t)e * ((size_t)FFN_DIM * H_DIM);
#pragma unroll
    for (int i = 0; i < 4; i++) {
        int idx = tid + (i << 9);
        int r = idx >> 5, c = idx & 31;
        bdst[i] = (uint32_t)(r * 512 + ((((c & 24) | ((c ^ r) & 7))) << 4));
        bsrc[i] = w2e + (size_t)r * H_DIM + n0 + c * 8;
    }

    auto load_stage = [&](int t) {
        uint32_t ab = sb + (uint32_t)(t & 3) * STAGE_BYTES;
        uint32_t bb = ab + 16384u;
        int k0 = t * 64;
#pragma unroll
        for (int i = 0; i < 2; i++) cpa16(ab + adst[i], asrc[i] + k0);
#pragma unroll
        for (int i = 0; i < 4; i++) cpa16(bb + bdst[i], bsrc[i] + (size_t)k0 * H_DIM);
    };

    uint32_t aoffr = (uint32_t)((wm * 32 + (lane & 15)) * 128);
    uint32_t cxb = (uint32_t)(lane >> 4), rx = (uint32_t)(lane & 7);
    uint32_t klocal = ((lane >> 3) & 1) * 8 + (lane & 7);
    uint32_t bbase[4];
#pragma unroll
    for (int p = 0; p < 4; p++) {
        uint32_t unit = (uint32_t)(wn * 8 + p * 2) + (uint32_t)(lane >> 4);
        uint32_t usw = (unit & 24) | ((unit ^ (lane & 7)) & 7);
        bbase[p] = klocal * 512 + (usw << 4);
    }

    float acc[2][8][4] = {};

    load_stage(0); CPCOMMIT();
    load_stage(1); CPCOMMIT();
    load_stage(2); CPCOMMIT();

    const int NS = FFN_DIM / 64;  // 22
    for (int s = 0; s < NS; s++) {
        CPWAIT2();
        __syncthreads();
        if (s + 3 < NS) load_stage(s + 3);
        CPCOMMIT();
        uint32_t ab = sb + (uint32_t)(s & 3) * STAGE_BYTES;
        uint32_t bb = ab + 16384u;
#pragma unroll
        for (int kk = 0; kk < 4; kk++) {
            uint32_t cx = ((((uint32_t)kk << 1) + cxb) ^ rx) << 4;
            uint32_t af[2][4], bf[4][4];
#pragma unroll
            for (int mt = 0; mt < 2; mt++) ldm4(af[mt], ab + aoffr + mt * 2048 + cx);
#pragma unroll
            for (int p = 0; p < 4; p++) ldm4t(bf[p], bb + bbase[p] + (uint32_t)kk * 8192);
#pragma unroll
            for (int mt = 0; mt < 2; mt++)
#pragma unroll
                for (int p = 0; p < 4; p++) {
                    mma16(acc[mt][2 * p],     af[mt], bf[p][0], bf[p][1]);
                    mma16(acc[mt][2 * p + 1], af[mt], bf[p][2], bf[p][3]);
                }
        }
    }

    int gid = lane >> 2, tig = lane & 3;
#pragma unroll
    for (int mt = 0; mt < 2; mt++) {
        int r1 = m0 + wm * 32 + mt * 16 + gid;
#pragma unroll
        for (int j = 0; j < 8; j++) {
            int col = n0 + wn * 64 + j * 8 + tig * 2;
            if (r1 < cnt) {
                float2 o = make_float2(acc[mt][j][0], acc[mt][j][1]);
                *(float2*)&g_y[(size_t)(base + r1) * H_DIM + col] = o;
            }
            if (r1 + 8 < cnt) {
                float2 o = make_float2(acc[mt][j][2], acc[mt][j][3]);
                *(float2*)&g_y[(size_t)(base + r1 + 8) * H_DIM + col] = o;
            }
        }
    }
}

// ---------------- combine: out[t] = w0*Y[slot0] + w1*Y[slot1] --------------
__global__ void __launch_bounds__(256) combine_kernel(float* __restrict__ out)
{
    int t = blockIdx.x;
    int s0 = g_slot[2 * t], s1 = g_slot[2 * t + 1];
    float w0 = g_topk_w[2 * t], w1 = g_topk_w[2 * t + 1];
    const float* y0 = g_y + (size_t)s0 * H_DIM;
    const float* y1 = g_y + (size_t)s1 * H_DIM;
    float* orow = out + (size_t)t * H_DIM;

    int h = threadIdx.x * 4;
    float4 a = *(const float4*)(y0 + h);
    float4 b = *(const float4*)(y1 + h);
    float4 o;
    o.x = w0 * a.x + w1 * b.x;
    o.y = w0 * a.y + w1 * b.y;
    o.z = w0 * a.z + w1 * b.z;
    o.w = w0 * a.w + w1 * b.w;
    *(float4*)(orow + h) = o;
}

// ---------------- launch ----------------------------------------------------
extern "C" void kernel_launch(void* const* d_in, const int* in_sizes, int n_in,
                              void* d_out, int out_size)
{
    const float* hidden = (const float*)d_in[0];   // [S, B, H] == [T, H]
    const float* gate_w = (const float*)d_in[1];   // [E, H]
    const float* w1     = (const float*)d_in[2];   // [E, H, 2*FFN]
    const float* w2     = (const float*)d_in[3];   // [E, FFN, H]
    float* out          = (float*)d_out;

    static cudaStream_t sW = nullptr;
    static cudaEvent_t ev_fork = nullptr, ev_w1 = nullptr, ev_w2 = nullptr;
    static bool attr_done = false;
    if (!sW) {
        cudaStreamCreateWithFlags(&sW, cudaStreamNonBlocking);
        cudaEventCreateWithFlags(&ev_fork, cudaEventDisableTiming);
        cudaEventCreateWithFlags(&ev_w1, cudaEventDisableTiming);
        cudaEventCreateWithFlags(&ev_w2, cudaEventDisableTiming);
    }
    if (!attr_done) {
        cudaFuncSetAttribute(gemm1_kernel, cudaFuncAttributeMaxDynamicSharedMemorySize, SMEM_BYTES);
        cudaFuncSetAttribute(gemm2_kernel, cudaFuncAttributeMaxDynamicSharedMemorySize, SMEM_BYTES);
        attr_done = true;
    }

    __half* w1h; cudaGetSymbolAddress((void**)&w1h, g_w1h);
    __half* w2h; cudaGetSymbolAddress((void**)&w2h, g_w2h);

    // Fork: weight casts on sW (w1 first — gemm1 only needs w1h).
    cudaEventRecord(ev_fork, 0);
    cudaStreamWaitEvent(sW, ev_fork, 0);
    convW_kernel<<<2048, 256, 0, sW>>>(w1, w1h, (size_t)E_DIM * H_DIM * FFN2_DIM / 4);
    cudaEventRecord(ev_w1, sW);
    convW_kernel<<<2048, 256, 0, sW>>>(w2, w2h, (size_t)E_DIM * FFN_DIM * H_DIM / 4);
    cudaEventRecord(ev_w2, sW);

    init_kernel<<<1, 32>>>();
    gate_kernel<<<T_DIM, 256>>>(hidden, gate_w);   // writes g_xh + counts
    scatter_kernel<<<E_DIM, 256>>>();

    // GEMMs on stream 0 (full z=8 grids — single ragged tail each).
    cudaStreamWaitEvent(0, ev_w1, 0);
    gemm1_kernel<<<dim3(FFN_DIM / 128, NPAIR / 128, E_DIM), GTHREADS, SMEM_BYTES>>>();
    cudaStreamWaitEvent(0, ev_w2, 0);
    gemm2_kernel<<<dim3(H_DIM / 256, NPAIR / 128, E_DIM), GTHREADS, SMEM_BYTES>>>();
    combine_kernel<<<T_DIM, 256>>>(out);
}

// round 15
// speedup vs baseline: 1.2493x; 1.0040x over previous
#include <cuda_runtime.h>
#include <cuda_fp16.h>
#include <cstdint>

// Problem shapes (fixed by the dataset)
#define T_DIM 2048
#define H_DIM 1024
#define E_DIM 8
#define FFN_DIM 1408
#define FFN2_DIM 2816
#define NPAIR 4096
#define NPAD (NPAIR + 128)

// ---------------- scratch (device globals) ----------------------------------
__device__ int   g_topk_idx[T_DIM * 2];
__device__ float g_topk_w[T_DIM * 2];
__device__ int   g_tok[NPAIR];
__device__ int   g_slot[T_DIM * 2];
__device__ int   g_base[E_DIM];
__device__ int   g_cnt[E_DIM];
__device__ __align__(16) __half g_xh[(size_t)T_DIM * H_DIM];               // token rows (half)
__device__ __align__(16) __half g_acth[(size_t)NPAD * FFN_DIM];
__device__ __align__(16) float  g_y[(size_t)NPAIR * H_DIM];
__device__ __align__(16) __half g_w1h[(size_t)E_DIM * H_DIM * FFN2_DIM];   // native [k][n]
__device__ __align__(16) __half g_w2h[(size_t)E_DIM * FFN_DIM * H_DIM];    // native [k][n]

// ---------------- helpers ----------------------------------------------------
__device__ __forceinline__ uint32_t smem_u32(const void* p) {
    uint32_t a;
    asm("{ .reg .u64 t; cvta.to.shared.u64 t, %1; cvt.u32.u64 %0, t; }"
        : "=r"(a) : "l"(p));
    return a;
}
__device__ __forceinline__ void cpa16(uint32_t dst, const void* src) {
    asm volatile("cp.async.cg.shared.global [%0], [%1], 16;" :: "r"(dst), "l"(src));
}
#define CPCOMMIT() asm volatile("cp.async.commit_group;" ::: "memory")
#define CPWAIT2()  asm volatile("cp.async.wait_group 2;" ::: "memory")

__device__ __forceinline__ void ldm4(uint32_t* f, uint32_t a) {
    asm volatile("ldmatrix.sync.aligned.m8n8.x4.shared.b16 {%0,%1,%2,%3}, [%4];"
                 : "=r"(f[0]), "=r"(f[1]), "=r"(f[2]), "=r"(f[3]) : "r"(a));
}
__device__ __forceinline__ void ldm4t(uint32_t* f, uint32_t a) {
    asm volatile("ldmatrix.sync.aligned.m8n8.x4.trans.shared.b16 {%0,%1,%2,%3}, [%4];"
                 : "=r"(f[0]), "=r"(f[1]), "=r"(f[2]), "=r"(f[3]) : "r"(a));
}
__device__ __forceinline__ void mma16(float* c, const uint32_t* a,
                                      uint32_t b0, uint32_t b1) {
    asm volatile(
        "mma.sync.aligned.m16n8k16.row.col.f32.f16.f16.f32 "
        "{%0,%1,%2,%3}, {%4,%5,%6,%7}, {%8,%9}, {%0,%1,%2,%3};"
        : "+f"(c[0]), "+f"(c[1]), "+f"(c[2]), "+f"(c[3])
        : "r"(a[0]), "r"(a[1]), "r"(a[2]), "r"(a[3]), "r"(b0), "r"(b1));
}

// stage: A [128 m][64 k] half = 16KB at +0 ; B [64 k][256 n] half = 32KB at +16384
#define STAGE_BYTES 49152u
#define NSTAGE 4
#define SMEM_BYTES (NSTAGE * STAGE_BYTES)   // 196608
#define GTHREADS 512

// ---------------- init: zero per-expert counters -----------------------------
__global__ void init_kernel()
{
    if (threadIdx.x < E_DIM) g_cnt[threadIdx.x] = 0;
}

// ---------------- gate: single-pass dot(8 experts) + f16 convert + counts ----
__global__ void __launch_bounds__(256) gate_kernel(
    const float* __restrict__ x, const float* __restrict__ gw)
{
    int t = blockIdx.x;
    int wid = threadIdx.x >> 5, lane = threadIdx.x & 31;
    __shared__ float sred[E_DIM][8];
    __shared__ float sc[E_DIM];

    // one float4 of the token row per thread (only read of x)
    float4 v = ((const float4*)(x + (size_t)t * H_DIM))[threadIdx.x];
    {
        __half2* d = (__half2*)(g_xh + (size_t)t * H_DIM);
        d[threadIdx.x * 2]     = __floats2half2_rn(v.x, v.y);
        d[threadIdx.x * 2 + 1] = __floats2half2_rn(v.z, v.w);
    }

    // partial dot against all 8 gate rows (gate_w is 32KB, L1-hot)
    float p[E_DIM];
#pragma unroll
    for (int e = 0; e < E_DIM; e++) {
        float4 g = ((const float4*)(gw + (size_t)e * H_DIM))[threadIdx.x];
        p[e] = v.x * g.x + v.y * g.y + v.z * g.z + v.w * g.w;
    }
    // warp reduce each expert
#pragma unroll
    for (int e = 0; e < E_DIM; e++) {
        float s = p[e];
#pragma unroll
        for (int o = 16; o; o >>= 1) s += __shfl_xor_sync(0xffffffffu, s, o);
        if (lane == 0) sred[e][wid] = s;
    }
    __syncthreads();
    if (threadIdx.x < E_DIM) {
        float s = 0.f;
#pragma unroll
        for (int w = 0; w < 8; w++) s += sred[threadIdx.x][w];
        sc[threadIdx.x] = s;
    }
    __syncthreads();

    if (threadIdx.x == 0) {
        float m = -1e30f;
#pragma unroll
        for (int e = 0; e < E_DIM; e++) m = fmaxf(m, sc[e]);
        float p2[E_DIM], den = 0.f;
#pragma unroll
        for (int e = 0; e < E_DIM; e++) { p2[e] = __expf(sc[e] - m); den += p2[e]; }
        int i0 = 0;
#pragma unroll
        for (int e = 1; e < E_DIM; e++) if (p2[e] > p2[i0]) i0 = e;
        int i1 = -1;
#pragma unroll
        for (int e = 0; e < E_DIM; e++)
            if (e != i0 && (i1 < 0 || p2[e] > p2[i1])) i1 = e;
        float q0 = p2[i0] / den, q1 = p2[i1] / den;
        float wsum = q0 + q1 + 1e-20f;
        g_topk_idx[2 * t]     = i0;
        g_topk_idx[2 * t + 1] = i1;
        g_topk_w[2 * t]       = q0 / wsum;
        g_topk_w[2 * t + 1]   = q1 / wsum;
        atomicAdd(&g_cnt[i0], 1);
        atomicAdd(&g_cnt[i1], 1);
    }
}

// ---------------- scatter: 8 blocks (one expert each), stable compaction ----
__global__ void __launch_bounds__(256) scatter_kernel()
{
    int e = blockIdx.x;
    int wid = threadIdx.x >> 5, lane = threadIdx.x & 31;
    __shared__ int swcnt[8];
    __shared__ int sbase;

    int c = 0;
#pragma unroll
    for (int i = 0; i < 8; i++) {
        int t = wid * 256 + i * 32 + lane;
        bool m = (g_topk_idx[2 * t] == e) || (g_topk_idx[2 * t + 1] == e);
        unsigned b = __ballot_sync(0xffffffffu, m);
        c += __popc(b);
    }
    if (lane == 0) swcnt[wid] = c;
    __syncthreads();
    if (threadIdx.x == 0) {
        int b = 0;
        for (int i = 0; i < e; i++) b += g_cnt[i];
        g_base[e] = b;
        sbase = b;
        int acc = 0;
        for (int w = 0; w < 8; w++) { int cc = swcnt[w]; swcnt[w] = acc; acc += cc; }
    }
    __syncthreads();

    int pos = sbase + swcnt[wid];
#pragma unroll
    for (int i = 0; i < 8; i++) {
        int t = wid * 256 + i * 32 + lane;
        int k = -1;
        if (g_topk_idx[2 * t] == e) k = 0;
        else if (g_topk_idx[2 * t + 1] == e) k = 1;
        unsigned b = __ballot_sync(0xffffffffu, k >= 0);
        int off = __popc(b & ((1u << lane) - 1u));
        if (k >= 0) {
            g_tok[pos + off] = t;
            g_slot[2 * t + k] = pos + off;
        }
        pos += __popc(b);
    }
}

// ---------------- streaming f32 -> f16 cast ---------------------------------
__global__ void __launch_bounds__(256) convW_kernel(
    const float* __restrict__ src, __half* __restrict__ dst, size_t n4)
{
    size_t i = (size_t)blockIdx.x * blockDim.x + threadIdx.x;
    size_t stride = (size_t)gridDim.x * blockDim.x;
    for (; i < n4; i += stride) {
        float4 v = ((const float4*)src)[i];
        __half2 h0 = __floats2half2_rn(v.x, v.y);
        __half2 h1 = __floats2half2_rn(v.z, v.w);
        ((uint2*)dst)[i] = make_uint2(*(uint32_t*)&h0, *(uint32_t*)&h1);
    }
}

// ---------------- GEMM1: x_tok rows @ w1h([k][n]) -> swiglu -> g_acth -------
// CTA: 128 M x 128 FFN cols; 512 threads, 16 warps (4m x 4n), warp 32 x 64.
__global__ void __launch_bounds__(GTHREADS) gemm1_kernel()
{
    int e = blockIdx.z;
    int cnt = g_cnt[e];
    int m0 = blockIdx.y * 128;
    if (m0 >= cnt) return;
    int base = g_base[e];
    int n0 = blockIdx.x * 128;

    extern __shared__ char smem[];
    uint32_t sb = smem_u32(smem);
    int tid = threadIdx.x, lane = tid & 31, wid = tid >> 5;
    int wm = wid >> 2, wn = wid & 3;     // 4 x 4 warps

    uint32_t adst[2]; const __half* asrc[2];
#pragma unroll
    for (int i = 0; i < 2; i++) {
        int idx = tid + (i << 9);
        int r = idx >> 3, c = idx & 7;
        adst[i] = (uint32_t)(r * 128 + ((c ^ (r & 7)) << 4));
        int pr = base + m0 + r;
        if (pr > NPAIR - 1) pr = NPAIR - 1;
        int tok = g_tok[pr];
        asrc[i] = g_xh + (size_t)tok * H_DIM + c * 8;
    }
    uint32_t bdst[4]; const __half* bsrc[4];
    const __half* w1e = g_w1h + (size_t)e * ((size_t)H_DIM * FFN2_DIM);
#pragma unroll
    for (int i = 0; i < 4; i++) {
        int idx = tid + (i << 9);
        int r = idx >> 5, c = idx & 31;
        bdst[i] = (uint32_t)(r * 512 + ((((c & 24) | ((c ^ r) & 7))) << 4));
        int col = (c < 16) ? (n0 + c * 8) : (FFN_DIM + n0 + (c - 16) * 8);
        bsrc[i] = w1e + (size_t)r * FFN2_DIM + col;
    }

    auto load_stage = [&](int t) {
        uint32_t ab = sb + (uint32_t)(t & 3) * STAGE_BYTES;
        uint32_t bb = ab + 16384u;
        int k0 = t * 64;
#pragma unroll
        for (int i = 0; i < 2; i++) cpa16(ab + adst[i], asrc[i] + k0);
#pragma unroll
        for (int i = 0; i < 4; i++) cpa16(bb + bdst[i], bsrc[i] + (size_t)k0 * FFN2_DIM);
    };

    uint32_t aoffr = (uint32_t)((wm * 32 + (lane & 15)) * 128);
    uint32_t cxb = (uint32_t)(lane >> 4), rx = (uint32_t)(lane & 7);
    uint32_t klocal = ((lane >> 3) & 1) * 8 + (lane & 7);
    uint32_t bbase[4];
#pragma unroll
    for (int p = 0; p < 4; p++) {
        uint32_t u = (p < 2) ? (uint32_t)(wn * 4 + p * 2)
                             : (uint32_t)(16 + wn * 4 + (p - 2) * 2);
        uint32_t unit = u + (uint32_t)(lane >> 4);
        uint32_t usw = (unit & 24) | ((unit ^ (lane & 7)) & 7);
        bbase[p] = klocal * 512 + (usw << 4);
    }

    float acc[2][8][4] = {};

    load_stage(0); CPCOMMIT();
    load_stage(1); CPCOMMIT();
    load_stage(2); CPCOMMIT();

    const int NS = H_DIM / 64;  // 16
    for (int s = 0; s < NS; s++) {
        CPWAIT2();
        __syncthreads();
        if (s + 3 < NS) load_stage(s + 3);
        CPCOMMIT();
        uint32_t ab = sb + (uint32_t)(s & 3) * STAGE_BYTES;
        uint32_t bb = ab + 16384u;
#pragma unroll
        for (int kk = 0; kk < 4; kk++) {
            uint32_t cx = ((((uint32_t)kk << 1) + cxb) ^ rx) << 4;
            uint32_t af[2][4], bf[4][4];
#pragma unroll
            for (int mt = 0; mt < 2; mt++) ldm4(af[mt], ab + aoffr + mt * 2048 + cx);
#pragma unroll
            for (int p = 0; p < 4; p++) ldm4t(bf[p], bb + bbase[p] + (uint32_t)kk * 8192);
#pragma unroll
            for (int mt = 0; mt < 2; mt++)
#pragma unroll
                for (int p = 0; p < 4; p++) {
                    mma16(acc[mt][2 * p],     af[mt], bf[p][0], bf[p][1]);
                    mma16(acc[mt][2 * p + 1], af[mt], bf[p][2], bf[p][3]);
                }
        }
    }

    // epilogue: swiglu, store half
    int gid = lane >> 2, tig = lane & 3;
#pragma unroll
    for (int mt = 0; mt < 2; mt++) {
        int r1 = m0 + wm * 32 + mt * 16 + gid;
#pragma unroll
        for (int j = 0; j < 4; j++) {
            int col = n0 + wn * 32 + j * 8 + tig * 2;
            float g0 = acc[mt][j][0], g1 = acc[mt][j][1];
            float u0 = acc[mt][j + 4][0], u1 = acc[mt][j + 4][1];
            if (r1 < cnt) {
                __half2 h = __floats2half2_rn(g0 * u0 / (1.f + __expf(-g0)),
                                              g1 * u1 / (1.f + __expf(-g1)));
                *(__half2*)&g_acth[(size_t)(base + r1) * FFN_DIM + col] = h;
            }
            float g2 = acc[mt][j][2], g3 = acc[mt][j][3];
            float u2 = acc[mt][j + 4][2], u3 = acc[mt][j + 4][3];
            if (r1 + 8 < cnt) {
                __half2 h = __floats2half2_rn(g2 * u2 / (1.f + __expf(-g2)),
                                              g3 * u3 / (1.f + __expf(-g3)));
                *(__half2*)&g_acth[(size_t)(base + r1 + 8) * FFN_DIM + col] = h;
            }
        }
    }
}

// ---------------- GEMM2: g_acth[128,1408] @ w2h([k][n]) -> g_y --------------
// CTA: 128 M x 256 N; 512 threads, 16 warps (4m x 4n), warp 32 x 64.
__global__ void __launch_bounds__(GTHREADS) gemm2_kernel()
{
    int e = blockIdx.z;
    int cnt = g_cnt[e];
    int m0 = blockIdx.y * 128;
    if (m0 >= cnt) return;
    int base = g_base[e];
    int n0 = blockIdx.x * 256;

    extern __shared__ char smem[];
    uint32_t sb = smem_u32(smem);
    int tid = threadIdx.x, lane = tid & 31, wid = tid >> 5;
    int wm = wid >> 2, wn = wid & 3;

    uint32_t adst[2]; const __half* asrc[2];
#pragma unroll
    for (int i = 0; i < 2; i++) {
        int idx = tid + (i << 9);
        int r = idx >> 3, c = idx & 7;
        adst[i] = (uint32_t)(r * 128 + ((c ^ (r & 7)) << 4));
        asrc[i] = g_acth + (size_t)(base + m0 + r) * FFN_DIM + c * 8;
    }
    uint32_t bdst[4]; const __half* bsrc[4];
    const __half* w2e = g_w2h + (size_t)e * ((size_t)FFN_DIM * H_DIM);
#pragma unroll
    for (int i = 0; i < 4; i++) {
        int idx = tid + (i << 9);
        int r = idx >> 5, c = idx & 31;
        bdst[i] = (uint32_t)(r * 512 + ((((c & 24) | ((c ^ r) & 7))) << 4));
        bsrc[i] = w2e + (size_t)r * H_DIM + n0 + c * 8;
    }

    auto load_stage = [&](int t) {
        uint32_t ab = sb + (uint32_t)(t & 3) * STAGE_BYTES;
        uint32_t bb = ab + 16384u;
        int k0 = t * 64;
#pragma unroll
        for (int i = 0; i < 2; i++) cpa16(ab + adst[i], asrc[i] + k0);
#pragma unroll
        for (int i = 0; i < 4; i++) cpa16(bb + bdst[i], bsrc[i] + (size_t)k0 * H_DIM);
    };

    uint32_t aoffr = (uint32_t)((wm * 32 + (lane & 15)) * 128);
    uint32_t cxb = (uint32_t)(lane >> 4), rx = (uint32_t)(lane & 7);
    uint32_t klocal = ((lane >> 3) & 1) * 8 + (lane & 7);
    uint32_t bbase[4];
#pragma unroll
    for (int p = 0; p < 4; p++) {
        uint32_t unit = (uint32_t)(wn * 8 + p * 2) + (uint32_t)(lane >> 4);
        uint32_t usw = (unit & 24) | ((unit ^ (lane & 7)) & 7);
        bbase[p] = klocal * 512 + (usw << 4);
    }

    float acc[2][8][4] = {};

    load_stage(0); CPCOMMIT();
    load_stage(1); CPCOMMIT();
    load_stage(2); CPCOMMIT();

    const int NS = FFN_DIM / 64;  // 22
    for (int s = 0; s < NS; s++) {
        CPWAIT2();
        __syncthreads();
        if (s + 3 < NS) load_stage(s + 3);
        CPCOMMIT();
        uint32_t ab = sb + (uint32_t)(s & 3) * STAGE_BYTES;
        uint32_t bb = ab + 16384u;
#pragma unroll
        for (int kk = 0; kk < 4; kk++) {
            uint32_t cx = ((((uint32_t)kk << 1) + cxb) ^ rx) << 4;
            uint32_t af[2][4], bf[4][4];
#pragma unroll
            for (int mt = 0; mt < 2; mt++) ldm4(af[mt], ab + aoffr + mt * 2048 + cx);
#pragma unroll
            for (int p = 0; p < 4; p++) ldm4t(bf[p], bb + bbase[p] + (uint32_t)kk * 8192);
#pragma unroll
            for (int mt = 0; mt < 2; mt++)
#pragma unroll
                for (int p = 0; p < 4; p++) {
                    mma16(acc[mt][2 * p],     af[mt], bf[p][0], bf[p][1]);
                    mma16(acc[mt][2 * p + 1], af[mt], bf[p][2], bf[p][3]);
                }
        }
    }

    int gid = lane >> 2, tig = lane & 3;
#pragma unroll
    for (int mt = 0; mt < 2; mt++) {
        int r1 = m0 + wm * 32 + mt * 16 + gid;
#pragma unroll
        for (int j = 0; j < 8; j++) {
            int col = n0 + wn * 64 + j * 8 + tig * 2;
            if (r1 < cnt) {
                float2 o = make_float2(acc[mt][j][0], acc[mt][j][1]);
                *(float2*)&g_y[(size_t)(base + r1) * H_DIM + col] = o;
            }
            if (r1 + 8 < cnt) {
                float2 o = make_float2(acc[mt][j][2], acc[mt][j][3]);
                *(float2*)&g_y[(size_t)(base + r1 + 8) * H_DIM + col] = o;
            }
        }
    }
}

// ---------------- combine: 4 tokens/block, MLP-8 ----------------------------
__global__ void __launch_bounds__(256) combine_kernel(float* __restrict__ out)
{
    int t0 = blockIdx.x * 4;
    int h = threadIdx.x * 4;
    const float4* y0p[4];
    const float4* y1p[4];
    float w0[4], w1[4];
#pragma unroll
    for (int j = 0; j < 4; j++) {
        int t = t0 + j;
        y0p[j] = (const float4*)(g_y + (size_t)g_slot[2 * t] * H_DIM + h);
        y1p[j] = (const float4*)(g_y + (size_t)g_slot[2 * t + 1] * H_DIM + h);
        w0[j] = g_topk_w[2 * t];
        w1[j] = g_topk_w[2 * t + 1];
    }
    float4 a[4], b[4];
#pragma unroll
    for (int j = 0; j < 4; j++) { a[j] = *y0p[j]; b[j] = *y1p[j]; }
#pragma unroll
    for (int j = 0; j < 4; j++) {
        float4 o;
        o.x = w0[j] * a[j].x + w1[j] * b[j].x;
        o.y = w0[j] * a[j].y + w1[j] * b[j].y;
        o.z = w0[j] * a[j].z + w1[j] * b[j].z;
        o.w = w0[j] * a[j].w + w1[j] * b[j].w;
        *(float4*)(out + (size_t)(t0 + j) * H_DIM + h) = o;
    }
}

// ---------------- launch ----------------------------------------------------
extern "C" void kernel_launch(void* const* d_in, const int* in_sizes, int n_in,
                              void* d_out, int out_size)
{
    const float* hidden = (const float*)d_in[0];   // [S, B, H] == [T, H]
    const float* gate_w = (const float*)d_in[1];   // [E, H]
    const float* w1     = (const float*)d_in[2];   // [E, H, 2*FFN]
    const float* w2     = (const float*)d_in[3];   // [E, FFN, H]
    float* out          = (float*)d_out;

    static cudaStream_t sW = nullptr;
    static cudaEvent_t ev_fork = nullptr, ev_w1 = nullptr, ev_w2 = nullptr;
    static bool attr_done = false;
    if (!sW) {
        cudaStreamCreateWithFlags(&sW, cudaStreamNonBlocking);
        cudaEventCreateWithFlags(&ev_fork, cudaEventDisableTiming);
        cudaEventCreateWithFlags(&ev_w1, cudaEventDisableTiming);
        cudaEventCreateWithFlags(&ev_w2, cudaEventDisableTiming);
    }
    if (!attr_done) {
        cudaFuncSetAttribute(gemm1_kernel, cudaFuncAttributeMaxDynamicSharedMemorySize, SMEM_BYTES);
        cudaFuncSetAttribute(gemm2_kernel, cudaFuncAttributeMaxDynamicSharedMemorySize, SMEM_BYTES);
        attr_done = true;
    }

    __half* w1h; cudaGetSymbolAddress((void**)&w1h, g_w1h);
    __half* w2h; cudaGetSymbolAddress((void**)&w2h, g_w2h);

    // Fork: weight casts on sW (w1 first — gemm1 only needs w1h).
    cudaEventRecord(ev_fork, 0);
    cudaStreamWaitEvent(sW, ev_fork, 0);
    convW_kernel<<<2048, 256, 0, sW>>>(w1, w1h, (size_t)E_DIM * H_DIM * FFN2_DIM / 4);
    cudaEventRecord(ev_w1, sW);
    convW_kernel<<<2048, 256, 0, sW>>>(w2, w2h, (size_t)E_DIM * FFN_DIM * H_DIM / 4);
    cudaEventRecord(ev_w2, sW);

    init_kernel<<<1, 32>>>();
    gate_kernel<<<T_DIM, 256>>>(hidden, gate_w);   // writes g_xh + counts
    scatter_kernel<<<E_DIM, 256>>>();

    cudaStreamWaitEvent(0, ev_w1, 0);
    gemm1_kernel<<<dim3(FFN_DIM / 128, NPAIR / 128, E_DIM), GTHREADS, SMEM_BYTES>>>();
    cudaStreamWaitEvent(0, ev_w2, 0);
    gemm2_kernel<<<dim3(H_DIM / 256, NPAIR / 128, E_DIM), GTHREADS, SMEM_BYTES>>>();
    combine_kernel<<<T_DIM / 4, 256>>>(out);
}